// round 1
// baseline (speedup 1.0000x reference)
#include <cuda_runtime.h>
#include <math.h>

#define NN 50000
#define EE 800000
#define HIDD 128
#define CLSS 64
#define ATT 16

// ---------------- scratch (static device globals; no allocation) ----------------
__device__ float g_xw_a[NN * HIDD];
__device__ float g_xw_l[NN * HIDD];
__device__ float g_agg_a[NN * HIDD];
__device__ float g_agg_l[NN * HIDD];
__device__ float g_xbuf[NN * HIDD];
__device__ float g_ybuf[NN * CLSS];
__device__ float g_deg_a[NN];
__device__ float g_deg_l[NN];
__device__ float g_dinv_a[NN];
__device__ float g_dinv_l[NN];

// vectorized no-return atomic add (sm_90+)
__device__ __forceinline__ void red_add4(float* addr, float4 v) {
    asm volatile("red.global.add.v4.f32 [%0], {%1,%2,%3,%4};"
                 :: "l"(addr), "f"(v.x), "f"(v.y), "f"(v.z), "f"(v.w)
                 : "memory");
}

// ---------------- dense GEMM: out[N,128] = X[N,K] @ W[K,128] ----------------
template <int K>
__global__ void gemm_h(const float* __restrict__ X, const float* __restrict__ W,
                       float* __restrict__ out, int n) {
    const int ROWS = 32;
    __shared__ float sX[ROWS * K];
    int row0 = blockIdx.x * ROWS;
    for (int idx = threadIdx.x; idx < ROWS * K; idx += 128) {
        int r = idx / K, k = idx % K;
        int gr = row0 + r;
        sX[idx] = (gr < n) ? X[gr * K + k] : 0.f;
    }
    __syncthreads();
    int h = threadIdx.x;  // 128 threads = 128 output cols
    float acc[ROWS];
#pragma unroll
    for (int r = 0; r < ROWS; r++) acc[r] = 0.f;
    for (int k = 0; k < K; k++) {
        float w = __ldg(&W[k * HIDD + h]);
#pragma unroll
        for (int r = 0; r < ROWS; r++) acc[r] = fmaf(sX[r * K + k], w, acc[r]);
    }
#pragma unroll
    for (int r = 0; r < ROWS; r++) {
        int gr = row0 + r;
        if (gr < n) out[gr * HIDD + h] = acc[r];
    }
}

// ---------------- degree ----------------
__global__ void deg_init_k(float* da, float* dl, int n) {
    int i = blockIdx.x * blockDim.x + threadIdx.x;
    if (i < n) { da[i] = 1.f; dl[i] = 1.f; }  // self-loop weight 1 for both convs
}

__global__ void deg_edges_k(const int* __restrict__ col, const float* __restrict__ ew,
                            float* da, float* dl, int e) {
    int i = blockIdx.x * blockDim.x + threadIdx.x;
    if (i < e) {
        int c = col[i];
        atomicAdd(&da[c], 1.f);
        atomicAdd(&dl[c], ew[i]);
    }
}

__global__ void dinv_k(const float* __restrict__ dega, const float* __restrict__ degl,
                       float* dinva, float* dinvl, int n) {
    int i = blockIdx.x * blockDim.x + threadIdx.x;
    if (i < n) {
        float a = dega[i], l = degl[i];
        dinva[i] = (a > 0.f) ? rsqrtf(a) : 0.f;
        dinvl[i] = (l > 0.f) ? rsqrtf(l) : 0.f;
    }
}

// ---------------- agg init: bias + self-loop contribution ----------------
__global__ void agg_init_k(const float4* __restrict__ xwa, const float4* __restrict__ xwl,
                           const float* __restrict__ dinva, const float* __restrict__ dinvl,
                           const float* __restrict__ ba, const float* __restrict__ bl,
                           float4* agga, float4* aggl, int n) {
    int t = blockIdx.x * blockDim.x + threadIdx.x;
    if (t >= n * (HIDD / 4)) return;
    int i = t >> 5;
    int q = t & 31;
    float da = dinva[i]; da *= da;   // self-loop norm = dinv*1*dinv
    float dl = dinvl[i]; dl *= dl;
    float4 xa = __ldg(&xwa[t]);
    float4 xl = __ldg(&xwl[t]);
    float4 b4a = __ldg(&((const float4*)ba)[q]);
    float4 b4l = __ldg(&((const float4*)bl)[q]);
    agga[t] = make_float4(b4a.x + da * xa.x, b4a.y + da * xa.y,
                          b4a.z + da * xa.z, b4a.w + da * xa.w);
    aggl[t] = make_float4(b4l.x + dl * xl.x, b4l.y + dl * xl.y,
                          b4l.z + dl * xl.z, b4l.w + dl * xl.w);
}

// ---------------- edge scatter: warp per edge, both convs fused ----------------
__global__ void edge_scatter_k(const int* __restrict__ row, const int* __restrict__ col,
                               const float* __restrict__ ew,
                               const float* __restrict__ dinva, const float* __restrict__ dinvl,
                               const float4* __restrict__ xwa, const float4* __restrict__ xwl,
                               float* agga, float* aggl, int e) {
    int gt = blockIdx.x * blockDim.x + threadIdx.x;
    int eidx = gt >> 5;
    if (eidx >= e) return;
    int lane = threadIdx.x & 31;
    int r = __ldg(&row[eidx]);
    int c = __ldg(&col[eidx]);
    float w  = __ldg(&ew[eidx]);
    float na = __ldg(&dinva[r]) * __ldg(&dinva[c]);
    float nl = __ldg(&dinvl[r]) * w * __ldg(&dinvl[c]);
    float4 va = __ldg(&xwa[r * 32 + lane]);
    float4 vl = __ldg(&xwl[r * 32 + lane]);
    float4 ma = make_float4(na * va.x, na * va.y, na * va.z, na * va.w);
    float4 ml = make_float4(nl * vl.x, nl * vl.y, nl * vl.z, nl * vl.w);
    red_add4(agga + (size_t)c * HIDD + lane * 4, ma);
    red_add4(aggl + (size_t)c * HIDD + lane * 4, ml);
}

// ---------------- attention fuse: warp per node ----------------
__global__ void fuse_k(const float* __restrict__ za, const float* __restrict__ zl,
                       const float* __restrict__ ap1, const float* __restrict__ apb1,
                       const float* __restrict__ ap2,
                       float* __restrict__ xout, int do_relu, int n) {
    __shared__ float s_ap1t[ATT * HIDD];  // transposed: [j][k] -> conflict-free
    __shared__ float s_b[ATT], s_a2[ATT];
    for (int idx = threadIdx.x; idx < ATT * HIDD; idx += blockDim.x) {
        int j = idx >> 7, k = idx & 127;
        s_ap1t[idx] = ap1[k * ATT + j];
    }
    if (threadIdx.x < ATT) {
        s_b[threadIdx.x]  = apb1[threadIdx.x];
        s_a2[threadIdx.x] = ap2[threadIdx.x];
    }
    __syncthreads();
    int gt = blockIdx.x * blockDim.x + threadIdx.x;
    int node = gt >> 5;
    if (node >= n) return;
    int lane = threadIdx.x & 31;
    float z0[4], z1[4];
#pragma unroll
    for (int m = 0; m < 4; m++) {
        z0[m] = za[node * HIDD + lane + 32 * m];
        z1[m] = zl[node * HIDD + lane + 32 * m];
    }
    float w0 = 0.f, w1 = 0.f;
#pragma unroll
    for (int j = 0; j < ATT; j++) {
        float p0 = 0.f, p1 = 0.f;
#pragma unroll
        for (int m = 0; m < 4; m++) {
            float a = s_ap1t[j * HIDD + lane + 32 * m];
            p0 = fmaf(z0[m], a, p0);
            p1 = fmaf(z1[m], a, p1);
        }
#pragma unroll
        for (int o = 16; o > 0; o >>= 1) {
            p0 += __shfl_xor_sync(0xffffffffu, p0, o);
            p1 += __shfl_xor_sync(0xffffffffu, p1, o);
        }
        w0 = fmaf(tanhf(p0 + s_b[j]), s_a2[j], w0);
        w1 = fmaf(tanhf(p1 + s_b[j]), s_a2[j], w1);
    }
    float b0 = 1.f / (1.f + expf(w1 - w0));  // softmax over 2 views
    float b1 = 1.f - b0;
#pragma unroll
    for (int m = 0; m < 4; m++) {
        float v = b0 * z0[m] + b1 * z1[m];
        if (do_relu) v = fmaxf(v, 0.f);
        xout[node * HIDD + lane + 32 * m] = v;
    }
}

// ---------------- label head: y = sigmoid(X @ mW + mb) ----------------
__global__ void ygemm_k(const float* __restrict__ X, const float* __restrict__ mW,
                        const float* __restrict__ mb, float* __restrict__ out, int n) {
    const int ROWS = 32;
    __shared__ float sX[ROWS * HIDD];
    int row0 = blockIdx.x * ROWS;
    for (int idx = threadIdx.x; idx < ROWS * HIDD; idx += 64) {
        int r = idx >> 7, k = idx & 127;
        int gr = row0 + r;
        sX[idx] = (gr < n) ? X[gr * HIDD + k] : 0.f;
    }
    __syncthreads();
    int j = threadIdx.x;  // 64 threads = 64 cols
    float acc[ROWS];
#pragma unroll
    for (int r = 0; r < ROWS; r++) acc[r] = 0.f;
    for (int k = 0; k < HIDD; k++) {
        float w = __ldg(&mW[k * CLSS + j]);
#pragma unroll
        for (int r = 0; r < ROWS; r++) acc[r] = fmaf(sX[r * HIDD + k], w, acc[r]);
    }
    float bj = mb[j];
#pragma unroll
    for (int r = 0; r < ROWS; r++) {
        int gr = row0 + r;
        if (gr < n) out[gr * CLSS + j] = 1.f / (1.f + expf(-(acc[r] + bj)));
    }
}

// ---------------- host orchestration ----------------
extern "C" void kernel_launch(void* const* d_in, const int* in_sizes, int n_in,
                              void* d_out, int out_size) {
    const float* x_in  = (const float*)d_in[0];
    const float* y_in  = (const float*)d_in[1];
    const int*   row   = (const int*)d_in[2];
    const int*   col   = (const int*)d_in[3];
    const float* ews   = (const float*)d_in[4];  // [2, E]
    const float* W0    = (const float*)d_in[5];
    const float* b0    = (const float*)d_in[6];
    const float* W1    = (const float*)d_in[7];
    const float* b1    = (const float*)d_in[8];
    const float* Wl    = (const float*)d_in[9];
    const float* bl    = (const float*)d_in[10];
    const float* ap1   = (const float*)d_in[11];
    const float* apb1  = (const float*)d_in[12];
    const float* ap2   = (const float*)d_in[13];
    const float* mW    = (const float*)d_in[14];
    const float* mb    = (const float*)d_in[15];
    float* out = (float*)d_out;

    float *xw_a, *xw_l, *agg_a, *agg_l, *xbuf, *ybuf;
    float *deg_a, *deg_l, *dinv_a, *dinv_l;
    cudaGetSymbolAddress((void**)&xw_a,  g_xw_a);
    cudaGetSymbolAddress((void**)&xw_l,  g_xw_l);
    cudaGetSymbolAddress((void**)&agg_a, g_agg_a);
    cudaGetSymbolAddress((void**)&agg_l, g_agg_l);
    cudaGetSymbolAddress((void**)&xbuf,  g_xbuf);
    cudaGetSymbolAddress((void**)&ybuf,  g_ybuf);
    cudaGetSymbolAddress((void**)&deg_a, g_deg_a);
    cudaGetSymbolAddress((void**)&deg_l, g_deg_l);
    cudaGetSymbolAddress((void**)&dinv_a, g_dinv_a);
    cudaGetSymbolAddress((void**)&dinv_l, g_dinv_l);

    const float* convW[2] = {W0, W1};
    const float* convB[2] = {b0, b1};

    const int gemm_blocks = (NN + 31) / 32;           // 1563
    const int n_blocks    = (NN + 255) / 256;         // 196
    const int e_blocks    = (EE + 255) / 256;         // 3125
    const int nf_blocks   = (NN * 32 + 255) / 256;    // node*float4 threads
    const int ef_blocks   = (EE * 32 + 255) / 256;    // edge*lane threads

    for (int layer = 0; layer < 2; layer++) {
        const float* Xin = (layer == 0) ? x_in : xbuf;
        const float* Yin = (layer == 0) ? y_in : ybuf;
        const float* ew  = ews + (size_t)layer * EE;
        int last = (layer == 1);
        float* xout = last ? out : xbuf;
        float* yout = last ? (out + (size_t)NN * HIDD) : ybuf;

        gemm_h<HIDD><<<gemm_blocks, 128>>>(Xin, convW[layer], xw_a, NN);
        gemm_h<CLSS><<<gemm_blocks, 128>>>(Yin, Wl, xw_l, NN);

        deg_init_k<<<n_blocks, 256>>>(deg_a, deg_l, NN);
        deg_edges_k<<<e_blocks, 256>>>(col, ew, deg_a, deg_l, EE);
        dinv_k<<<n_blocks, 256>>>(deg_a, deg_l, dinv_a, dinv_l, NN);

        agg_init_k<<<nf_blocks, 256>>>((const float4*)xw_a, (const float4*)xw_l,
                                       dinv_a, dinv_l, convB[layer], bl,
                                       (float4*)agg_a, (float4*)agg_l, NN);

        edge_scatter_k<<<ef_blocks, 256>>>(row, col, ew, dinv_a, dinv_l,
                                           (const float4*)xw_a, (const float4*)xw_l,
                                           agg_a, agg_l, EE);

        fuse_k<<<nf_blocks, 256>>>(agg_a, agg_l, ap1, apb1, ap2,
                                   xout, last ? 0 : 1, NN);

        ygemm_k<<<gemm_blocks, 64>>>(xout, mW, mb, yout, NN);
    }
}

// round 2
// speedup vs baseline: 1.4428x; 1.4428x over previous
#include <cuda_runtime.h>
#include <math.h>

#define NN 50000
#define EE 800000
#define HIDD 128
#define CLSS 64
#define ATT 16

// ---------------- scratch (static device globals; no allocation) ----------------
__device__ float g_xw_a[NN * HIDD];      // dinva[src] * (X @ W)
__device__ float g_xw_l[NN * HIDD];      // dinvl[src] * (Y @ Wl)
__device__ float g_xbuf[NN * HIDD];
__device__ float g_ybuf[NN * CLSS];
__device__ int   g_counts[NN];
__device__ int   g_off[NN + 1];
__device__ int   g_cursor[NN];
__device__ int   g_csr_src[EE];
__device__ float g_csr_w0[EE];
__device__ float g_csr_w1[EE];
__device__ float g_dinva[NN];
__device__ float g_dinvl0[NN];
__device__ float g_dinvl1[NN];
__device__ float g_degl0[NN];
__device__ float g_degl1[NN];

// ---------------- setup: histogram + degrees ----------------
__global__ void hist_init_k(int* counts, float* degl0, float* degl1, int n) {
    int i = blockIdx.x * blockDim.x + threadIdx.x;
    if (i < n) { counts[i] = 0; degl0[i] = 1.f; degl1[i] = 1.f; }  // self-loop w=1
}

__global__ void hist_k(const int* __restrict__ col,
                       const float* __restrict__ ew0, const float* __restrict__ ew1,
                       int* counts, float* degl0, float* degl1, int e) {
    int i = blockIdx.x * blockDim.x + threadIdx.x;
    if (i < e) {
        int c = col[i];
        atomicAdd(&counts[c], 1);
        atomicAdd(&degl0[c], ew0[i]);
        atomicAdd(&degl1[c], ew1[i]);
    }
}

__global__ void dinv_k(const int* __restrict__ counts,
                       const float* __restrict__ degl0, const float* __restrict__ degl1,
                       float* dinva, float* dinvl0, float* dinvl1, int n) {
    int i = blockIdx.x * blockDim.x + threadIdx.x;
    if (i < n) {
        dinva[i]  = rsqrtf(1.f + (float)counts[i]);
        dinvl0[i] = rsqrtf(degl0[i]);
        dinvl1[i] = rsqrtf(degl1[i]);
    }
}

// single-block scan over counts -> exclusive offsets (+ cursor copy)
__global__ void scan_k(const int* __restrict__ counts, int* off, int* cursor, int n) {
    __shared__ int s[1024];
    __shared__ int carry_s;
    int tid = threadIdx.x;
    if (tid == 0) carry_s = 0;
    __syncthreads();
    int nchunks = (n + 1023) / 1024;
    for (int ch = 0; ch < nchunks; ch++) {
        int i = ch * 1024 + tid;
        int v = (i < n) ? counts[i] : 0;
        s[tid] = v;
        __syncthreads();
        for (int d = 1; d < 1024; d <<= 1) {
            int t = (tid >= d) ? s[tid - d] : 0;
            __syncthreads();
            s[tid] += t;
            __syncthreads();
        }
        int excl = s[tid] - v + carry_s;
        if (i < n) { off[i] = excl; cursor[i] = excl; }
        __syncthreads();
        if (tid == 0) carry_s += s[1023];
        __syncthreads();
    }
    if (tid == 0) off[n] = carry_s;
}

__global__ void csr_scatter_k(const int* __restrict__ row, const int* __restrict__ col,
                              const float* __restrict__ ew0, const float* __restrict__ ew1,
                              int* cursor, int* csr_src, float* csr_w0, float* csr_w1, int e) {
    int i = blockIdx.x * blockDim.x + threadIdx.x;
    if (i < e) {
        int c = col[i];
        int p = atomicAdd(&cursor[c], 1);
        csr_src[p] = row[i];
        csr_w0[p] = ew0[i];
        csr_w1[p] = ew1[i];
    }
}

// ---------------- dense GEMM with packed fp32x2 FMA ----------------
// out[n, NOUT] = X[n, K] @ W[K, NOUT], then epilogue:
//   MODE 0: out *= scale_or_bias[row]   (per-row dinv scale)
//   MODE 1: out = sigmoid(out + scale_or_bias[col])
template <int K, int NOUT, int MODE>
__global__ void gemm_k(const float* __restrict__ X, const float* __restrict__ W,
                       const float* __restrict__ scale_or_bias,
                       float* __restrict__ out, int n) {
    const int ROWS = 32;
    __shared__ float sX[ROWS * K];
    int row0 = blockIdx.x * ROWS;
    for (int idx = threadIdx.x; idx < ROWS * K; idx += NOUT) {
        int r = idx / K, k = idx % K;
        int gr = row0 + r;
        sX[idx] = (gr < n) ? X[(size_t)gr * K + k] : 0.f;
    }
    __syncthreads();
    int h = threadIdx.x;  // NOUT threads = NOUT output cols
    unsigned long long acc[ROWS];
#pragma unroll
    for (int r = 0; r < ROWS; r++) acc[r] = 0ull;
    for (int kp = 0; kp < K / 2; kp++) {
        float w0 = __ldg(&W[(2 * kp) * NOUT + h]);
        float w1 = __ldg(&W[(2 * kp + 1) * NOUT + h]);
        unsigned long long wp;
        asm("mov.b64 %0, {%1, %2};" : "=l"(wp) : "f"(w0), "f"(w1));
#pragma unroll
        for (int r = 0; r < ROWS; r++) {
            unsigned long long xp =
                *reinterpret_cast<const unsigned long long*>(&sX[r * K + 2 * kp]);
            asm("fma.rn.f32x2 %0, %1, %2, %0;" : "+l"(acc[r]) : "l"(xp), "l"(wp));
        }
    }
#pragma unroll
    for (int r = 0; r < ROWS; r++) {
        int gr = row0 + r;
        if (gr < n) {
            float lo, hi;
            asm("mov.b64 {%0, %1}, %2;" : "=f"(lo), "=f"(hi) : "l"(acc[r]));
            float s = lo + hi;
            if (MODE == 0) {
                out[(size_t)gr * NOUT + h] = s * __ldg(&scale_or_bias[gr]);
            } else {
                float b = __ldg(&scale_or_bias[h]);
                out[(size_t)gr * NOUT + h] = 1.f / (1.f + expf(-(s + b)));
            }
        }
    }
}

// ---------------- fused gather + attention: warp per node ----------------
__global__ void gather_fuse_k(const float4* __restrict__ xwa, const float4* __restrict__ xwl,
                              const int* __restrict__ off, const int* __restrict__ csr_src,
                              const float* __restrict__ csr_w,
                              const float* __restrict__ dinva, const float* __restrict__ dinvl,
                              const float* __restrict__ b_adj, const float* __restrict__ b_lab,
                              const float* __restrict__ ap1, const float* __restrict__ apb1,
                              const float* __restrict__ ap2,
                              float4* __restrict__ xout, int do_relu, int n) {
    __shared__ float s_ap1t[ATT * HIDD];  // transposed: [j][feature]
    __shared__ float s_b[ATT], s_a2[ATT];
    for (int idx = threadIdx.x; idx < ATT * HIDD; idx += blockDim.x) {
        int j = idx >> 7, k = idx & 127;
        s_ap1t[idx] = ap1[k * ATT + j];
    }
    if (threadIdx.x < ATT) {
        s_b[threadIdx.x]  = apb1[threadIdx.x];
        s_a2[threadIdx.x] = ap2[threadIdx.x];
    }
    __syncthreads();

    int gt = blockIdx.x * blockDim.x + threadIdx.x;
    int node = gt >> 5;
    if (node >= n) return;
    int lane = threadIdx.x & 31;

    // self-loop contribution (weight 1 in both convs)
    float4 acc_a = __ldg(&xwa[node * 32 + lane]);
    float4 vsl   = __ldg(&xwl[node * 32 + lane]);
    float4 acc_l = vsl;

    int start = __ldg(&off[node]);
    int end   = __ldg(&off[node + 1]);
    int j = start;
    // full chunks of 32 edges
    for (; j + 32 <= end; j += 32) {
        int rr0  = __ldg(&csr_src[j + lane]);
        float ww0 = __ldg(&csr_w[j + lane]);
#pragma unroll 8
        for (int i = 0; i < 32; i++) {
            int rr  = __shfl_sync(0xffffffffu, rr0, i);
            float w = __shfl_sync(0xffffffffu, ww0, i);
            float4 va = __ldg(&xwa[rr * 32 + lane]);
            float4 vl = __ldg(&xwl[rr * 32 + lane]);
            acc_a.x += va.x; acc_a.y += va.y; acc_a.z += va.z; acc_a.w += va.w;
            acc_l.x = fmaf(w, vl.x, acc_l.x);
            acc_l.y = fmaf(w, vl.y, acc_l.y);
            acc_l.z = fmaf(w, vl.z, acc_l.z);
            acc_l.w = fmaf(w, vl.w, acc_l.w);
        }
    }
    // tail
    if (j < end) {
        int m = end - j;
        int rr0  = (lane < m) ? __ldg(&csr_src[j + lane]) : 0;
        float ww0 = (lane < m) ? __ldg(&csr_w[j + lane]) : 0.f;
#pragma unroll 4
        for (int i = 0; i < m; i++) {
            int rr  = __shfl_sync(0xffffffffu, rr0, i);
            float w = __shfl_sync(0xffffffffu, ww0, i);
            float4 va = __ldg(&xwa[rr * 32 + lane]);
            float4 vl = __ldg(&xwl[rr * 32 + lane]);
            acc_a.x += va.x; acc_a.y += va.y; acc_a.z += va.z; acc_a.w += va.w;
            acc_l.x = fmaf(w, vl.x, acc_l.x);
            acc_l.y = fmaf(w, vl.y, acc_l.y);
            acc_l.z = fmaf(w, vl.z, acc_l.z);
            acc_l.w = fmaf(w, vl.w, acc_l.w);
        }
    }

    // finalize conv outputs: z = dinv[dst] * acc + bias
    float da = __ldg(&dinva[node]);
    float dl = __ldg(&dinvl[node]);
    float4 ba4 = __ldg(&((const float4*)b_adj)[lane]);
    float4 bl4 = __ldg(&((const float4*)b_lab)[lane]);
    float z0[4], z1[4];
    z0[0] = fmaf(da, acc_a.x, ba4.x); z0[1] = fmaf(da, acc_a.y, ba4.y);
    z0[2] = fmaf(da, acc_a.z, ba4.z); z0[3] = fmaf(da, acc_a.w, ba4.w);
    z1[0] = fmaf(dl, acc_l.x, bl4.x); z1[1] = fmaf(dl, acc_l.y, bl4.y);
    z1[2] = fmaf(dl, acc_l.z, bl4.z); z1[3] = fmaf(dl, acc_l.w, bl4.w);

    // attention over the 2 views; lane owns features [4*lane, 4*lane+4)
    float w0 = 0.f, w1 = 0.f;
    const float4* ap1t4 = (const float4*)s_ap1t;
#pragma unroll
    for (int jj = 0; jj < ATT; jj++) {
        float4 a = ap1t4[jj * 32 + lane];
        float p0 = z0[0] * a.x + z0[1] * a.y + z0[2] * a.z + z0[3] * a.w;
        float p1 = z1[0] * a.x + z1[1] * a.y + z1[2] * a.z + z1[3] * a.w;
#pragma unroll
        for (int o = 16; o > 0; o >>= 1) {
            p0 += __shfl_xor_sync(0xffffffffu, p0, o);
            p1 += __shfl_xor_sync(0xffffffffu, p1, o);
        }
        w0 = fmaf(tanhf(p0 + s_b[jj]), s_a2[jj], w0);
        w1 = fmaf(tanhf(p1 + s_b[jj]), s_a2[jj], w1);
    }
    float beta0 = 1.f / (1.f + expf(w1 - w0));  // softmax over 2 views
    float beta1 = 1.f - beta0;

    float4 o4;
    o4.x = beta0 * z0[0] + beta1 * z1[0];
    o4.y = beta0 * z0[1] + beta1 * z1[1];
    o4.z = beta0 * z0[2] + beta1 * z1[2];
    o4.w = beta0 * z0[3] + beta1 * z1[3];
    if (do_relu) {
        o4.x = fmaxf(o4.x, 0.f); o4.y = fmaxf(o4.y, 0.f);
        o4.z = fmaxf(o4.z, 0.f); o4.w = fmaxf(o4.w, 0.f);
    }
    xout[node * 32 + lane] = o4;
}

// ---------------- host orchestration ----------------
extern "C" void kernel_launch(void* const* d_in, const int* in_sizes, int n_in,
                              void* d_out, int out_size) {
    const float* x_in  = (const float*)d_in[0];
    const float* y_in  = (const float*)d_in[1];
    const int*   row   = (const int*)d_in[2];
    const int*   col   = (const int*)d_in[3];
    const float* ews   = (const float*)d_in[4];  // [2, E]
    const float* W0    = (const float*)d_in[5];
    const float* b0    = (const float*)d_in[6];
    const float* W1    = (const float*)d_in[7];
    const float* b1    = (const float*)d_in[8];
    const float* Wl    = (const float*)d_in[9];
    const float* bl    = (const float*)d_in[10];
    const float* ap1   = (const float*)d_in[11];
    const float* apb1  = (const float*)d_in[12];
    const float* ap2   = (const float*)d_in[13];
    const float* mW    = (const float*)d_in[14];
    const float* mb    = (const float*)d_in[15];
    float* out = (float*)d_out;

    float *xw_a, *xw_l, *xbuf, *ybuf;
    float *dinva, *dinvl0, *dinvl1, *degl0, *degl1, *csr_w0, *csr_w1;
    int *counts, *off, *cursor, *csr_src;
    cudaGetSymbolAddress((void**)&xw_a,   g_xw_a);
    cudaGetSymbolAddress((void**)&xw_l,   g_xw_l);
    cudaGetSymbolAddress((void**)&xbuf,   g_xbuf);
    cudaGetSymbolAddress((void**)&ybuf,   g_ybuf);
    cudaGetSymbolAddress((void**)&counts, g_counts);
    cudaGetSymbolAddress((void**)&off,    g_off);
    cudaGetSymbolAddress((void**)&cursor, g_cursor);
    cudaGetSymbolAddress((void**)&csr_src, g_csr_src);
    cudaGetSymbolAddress((void**)&csr_w0, g_csr_w0);
    cudaGetSymbolAddress((void**)&csr_w1, g_csr_w1);
    cudaGetSymbolAddress((void**)&dinva,  g_dinva);
    cudaGetSymbolAddress((void**)&dinvl0, g_dinvl0);
    cudaGetSymbolAddress((void**)&dinvl1, g_dinvl1);
    cudaGetSymbolAddress((void**)&degl0,  g_degl0);
    cudaGetSymbolAddress((void**)&degl1,  g_degl1);

    const float* ew0 = ews;
    const float* ew1 = ews + EE;

    const int n_blocks  = (NN + 255) / 256;
    const int e_blocks  = (EE + 255) / 256;
    const int gemm_blk  = (NN + 31) / 32;
    const int gf_blocks = (NN * 32 + 255) / 256;  // warp per node

    // ---- one-time graph setup (runs each replay; ~50us) ----
    hist_init_k<<<n_blocks, 256>>>(counts, degl0, degl1, NN);
    hist_k<<<e_blocks, 256>>>(col, ew0, ew1, counts, degl0, degl1, EE);
    dinv_k<<<n_blocks, 256>>>(counts, degl0, degl1, dinva, dinvl0, dinvl1, NN);
    scan_k<<<1, 1024>>>(counts, off, cursor, NN);
    csr_scatter_k<<<e_blocks, 256>>>(row, col, ew0, ew1, cursor,
                                     csr_src, csr_w0, csr_w1, EE);

    const float* convW[2] = {W0, W1};
    const float* convB[2] = {b0, b1};
    const float* dinvl[2] = {dinvl0, dinvl1};
    const float* csrw[2]  = {csr_w0, csr_w1};

    for (int layer = 0; layer < 2; layer++) {
        const float* Xin = (layer == 0) ? x_in : xbuf;
        const float* Yin = (layer == 0) ? y_in : ybuf;
        int last = (layer == 1);
        float* xout = last ? out : xbuf;
        float* yout = last ? (out + (size_t)NN * HIDD) : ybuf;

        // xw = dinv[src] * (X @ W)  — dinv folded into GEMM epilogue
        gemm_k<HIDD, HIDD, 0><<<gemm_blk, HIDD>>>(Xin, convW[layer], dinva, xw_a, NN);
        gemm_k<CLSS, HIDD, 0><<<gemm_blk, HIDD>>>(Yin, Wl, dinvl[layer], xw_l, NN);

        gather_fuse_k<<<gf_blocks, 256>>>((const float4*)xw_a, (const float4*)xw_l,
                                          off, csr_src, csrw[layer],
                                          dinva, dinvl[layer],
                                          convB[layer], bl, ap1, apb1, ap2,
                                          (float4*)xout, last ? 0 : 1, NN);

        // y = sigmoid(x @ mW + mb)
        gemm_k<HIDD, CLSS, 1><<<gemm_blk, CLSS>>>(xout, mW, mb, yout, NN);
    }
}

// round 3
// speedup vs baseline: 2.0564x; 1.4253x over previous
#include <cuda_runtime.h>
#include <math.h>

#define NN 50000
#define EE 800000
#define HIDD 128
#define CLSS 64
#define ATT 16

// ---------------- scratch (static device globals; no allocation) ----------------
__device__ float g_xw_a[NN * HIDD];      // dinva[src] * (X @ W)
__device__ float g_xw_l[NN * HIDD];      // dinvl[src] * (Y @ Wl)
__device__ float g_xbuf[NN * HIDD];
__device__ float g_ybuf[NN * CLSS];
__device__ int   g_counts[NN];
__device__ int   g_off[NN + 1];
__device__ int   g_cursor[NN];
__device__ int   g_bsum[64];
__device__ int   g_csr_src[EE];
__device__ float g_csr_w0[EE];
__device__ float g_csr_w1[EE];
__device__ float g_dinva[NN];
__device__ float g_dinvl0[NN];
__device__ float g_dinvl1[NN];
__device__ float g_degl0[NN];
__device__ float g_degl1[NN];

// ---------------- setup: histogram + degrees ----------------
__global__ void hist_init_k(int* counts, float* degl0, float* degl1, int n) {
    int i = blockIdx.x * blockDim.x + threadIdx.x;
    if (i < n) { counts[i] = 0; degl0[i] = 1.f; degl1[i] = 1.f; }  // self-loop w=1
}

__global__ void hist_k(const int* __restrict__ col,
                       const float* __restrict__ ew0, const float* __restrict__ ew1,
                       int* counts, float* degl0, float* degl1, int e) {
    int i = blockIdx.x * blockDim.x + threadIdx.x;
    if (i < e) {
        int c = col[i];
        atomicAdd(&counts[c], 1);
        atomicAdd(&degl0[c], ew0[i]);
        atomicAdd(&degl1[c], ew1[i]);
    }
}

__global__ void dinv_k(const int* __restrict__ counts,
                       const float* __restrict__ degl0, const float* __restrict__ degl1,
                       float* dinva, float* dinvl0, float* dinvl1, int n) {
    int i = blockIdx.x * blockDim.x + threadIdx.x;
    if (i < n) {
        dinva[i]  = rsqrtf(1.f + (float)counts[i]);
        dinvl0[i] = rsqrtf(degl0[i]);
        dinvl1[i] = rsqrtf(degl1[i]);
    }
}

// ---------------- parallel exclusive scan (3 kernels) ----------------
__global__ void scan_partials_k(const int* __restrict__ counts, int* bsum, int n) {
    int i = blockIdx.x * 1024 + threadIdx.x;
    int v = (i < n) ? counts[i] : 0;
#pragma unroll
    for (int o = 16; o > 0; o >>= 1) v += __shfl_xor_sync(0xffffffffu, v, o);
    __shared__ int ws[32];
    if ((threadIdx.x & 31) == 0) ws[threadIdx.x >> 5] = v;
    __syncthreads();
    if (threadIdx.x < 32) {
        int s = ws[threadIdx.x];
#pragma unroll
        for (int o = 16; o > 0; o >>= 1) s += __shfl_xor_sync(0xffffffffu, s, o);
        if (threadIdx.x == 0) bsum[blockIdx.x] = s;
    }
}

__global__ void scan_bsums_k(int* bsum, int* off_last, int nb) {
    if (threadIdx.x == 0) {
        int acc = 0;
        for (int i = 0; i < nb; i++) { int t = bsum[i]; bsum[i] = acc; acc += t; }
        *off_last = acc;
    }
}

__global__ void scan_final_k(const int* __restrict__ counts, const int* __restrict__ bsum,
                             int* off, int* cursor, int n) {
    int i = blockIdx.x * 1024 + threadIdx.x;
    int v = (i < n) ? counts[i] : 0;
    int lane = threadIdx.x & 31, wid = threadIdx.x >> 5;
    int inc = v;
#pragma unroll
    for (int o = 1; o < 32; o <<= 1) {
        int t = __shfl_up_sync(0xffffffffu, inc, o);
        if (lane >= o) inc += t;
    }
    __shared__ int ws[32];
    if (lane == 31) ws[wid] = inc;
    __syncthreads();
    if (wid == 0) {
        int s = ws[lane];
        int si = s;
#pragma unroll
        for (int o = 1; o < 32; o <<= 1) {
            int t = __shfl_up_sync(0xffffffffu, si, o);
            if (lane >= o) si += t;
        }
        ws[lane] = si - s;  // exclusive warp offsets
    }
    __syncthreads();
    int excl = inc - v + ws[wid] + bsum[blockIdx.x];
    if (i < n) { off[i] = excl; cursor[i] = excl; }
}

__global__ void csr_scatter_k(const int* __restrict__ row, const int* __restrict__ col,
                              const float* __restrict__ ew0, const float* __restrict__ ew1,
                              int* cursor, int* csr_src, float* csr_w0, float* csr_w1, int e) {
    int i = blockIdx.x * blockDim.x + threadIdx.x;
    if (i < e) {
        int c = col[i];
        int p = atomicAdd(&cursor[c], 1);
        csr_src[p] = row[i];
        csr_w0[p] = ew0[i];
        csr_w1[p] = ew1[i];
    }
}

// ---------------- register-tiled GEMM ----------------
// out[n, NOUT] = X[n, K] @ W[K, NOUT]; epilogue:
//   MODE 0: out[r, :] = acc * sb[r]       (per-row dinv scale)
//   MODE 1: out[r, c] = sigmoid(acc + sb[c])
// Block: BM=64 rows x NOUT cols. Thread micro-tile: TM=8 x TN=4.
template <int K, int NOUT, int MODE>
__global__ void gemm_t(const float* __restrict__ X, const float* __restrict__ W,
                       const float* __restrict__ sb, float* __restrict__ out, int n) {
    constexpr int BM = 64;
    constexpr int TM = 8;
    constexpr int TN = 4;
    constexpr int TX = NOUT / TN;          // 32 or 16
    constexpr int NT = TX * (BM / TM);     // 256 or 128
    __shared__ float sX[BM * K];
    int row0 = blockIdx.x * BM;

    // load X tile (coalesced float4)
    for (int idx = threadIdx.x; idx < BM * (K / 4); idx += NT) {
        int r = idx / (K / 4), kq = idx % (K / 4);
        int gr = row0 + r;
        float4 v = (gr < n) ? __ldg(&((const float4*)X)[(size_t)gr * (K / 4) + kq])
                            : make_float4(0.f, 0.f, 0.f, 0.f);
        *(float4*)&sX[r * K + kq * 4] = v;
    }
    __syncthreads();

    int tx = threadIdx.x % TX;   // column group
    int ty = threadIdx.x / TX;   // row group
    const float* xrow = &sX[ty * TM * K];

    float acc[TM][TN];
#pragma unroll
    for (int m = 0; m < TM; m++)
#pragma unroll
        for (int c = 0; c < TN; c++) acc[m][c] = 0.f;

#pragma unroll 4
    for (int k = 0; k < K; k++) {
        float4 wv = __ldg((const float4*)&W[(size_t)k * NOUT + tx * TN]);
        float a[TM];
#pragma unroll
        for (int m = 0; m < TM; m++) a[m] = xrow[m * K + k];
#pragma unroll
        for (int m = 0; m < TM; m++) {
            acc[m][0] = fmaf(a[m], wv.x, acc[m][0]);
            acc[m][1] = fmaf(a[m], wv.y, acc[m][1]);
            acc[m][2] = fmaf(a[m], wv.z, acc[m][2]);
            acc[m][3] = fmaf(a[m], wv.w, acc[m][3]);
        }
    }

#pragma unroll
    for (int m = 0; m < TM; m++) {
        int gr = row0 + ty * TM + m;
        if (gr < n) {
            float4 o;
            if (MODE == 0) {
                float s = __ldg(&sb[gr]);
                o = make_float4(acc[m][0] * s, acc[m][1] * s, acc[m][2] * s, acc[m][3] * s);
            } else {
                float4 b = __ldg((const float4*)&sb[tx * TN]);
                o.x = 1.f / (1.f + expf(-(acc[m][0] + b.x)));
                o.y = 1.f / (1.f + expf(-(acc[m][1] + b.y)));
                o.z = 1.f / (1.f + expf(-(acc[m][2] + b.z)));
                o.w = 1.f / (1.f + expf(-(acc[m][3] + b.w)));
            }
            *(float4*)&out[(size_t)gr * NOUT + tx * TN] = o;
        }
    }
}

// ---------------- fused gather + attention: warp per node ----------------
__global__ void gather_fuse_k(const float4* __restrict__ xwa, const float4* __restrict__ xwl,
                              const int* __restrict__ off, const int* __restrict__ csr_src,
                              const float* __restrict__ csr_w,
                              const float* __restrict__ dinva, const float* __restrict__ dinvl,
                              const float* __restrict__ b_adj, const float* __restrict__ b_lab,
                              const float* __restrict__ ap1, const float* __restrict__ apb1,
                              const float* __restrict__ ap2,
                              float4* __restrict__ xout, int do_relu, int n) {
    __shared__ float s_ap1t[ATT * HIDD];  // transposed: [j][feature]
    __shared__ float s_b[ATT], s_a2[ATT];
    for (int idx = threadIdx.x; idx < ATT * HIDD; idx += blockDim.x) {
        int j = idx >> 7, k = idx & 127;
        s_ap1t[idx] = ap1[k * ATT + j];
    }
    if (threadIdx.x < ATT) {
        s_b[threadIdx.x]  = apb1[threadIdx.x];
        s_a2[threadIdx.x] = ap2[threadIdx.x];
    }
    __syncthreads();

    int gt = blockIdx.x * blockDim.x + threadIdx.x;
    int node = gt >> 5;
    if (node >= n) return;
    int lane = threadIdx.x & 31;

    // self-loop contribution (weight 1 in both convs)
    float4 acc_a = __ldg(&xwa[node * 32 + lane]);
    float4 acc_l = __ldg(&xwl[node * 32 + lane]);

    int start = __ldg(&off[node]);
    int end   = __ldg(&off[node + 1]);
    int j = start;
    for (; j + 32 <= end; j += 32) {
        int rr0   = __ldg(&csr_src[j + lane]);
        float ww0 = __ldg(&csr_w[j + lane]);
#pragma unroll 8
        for (int i = 0; i < 32; i++) {
            int rr  = __shfl_sync(0xffffffffu, rr0, i);
            float w = __shfl_sync(0xffffffffu, ww0, i);
            float4 va = __ldg(&xwa[rr * 32 + lane]);
            float4 vl = __ldg(&xwl[rr * 32 + lane]);
            acc_a.x += va.x; acc_a.y += va.y; acc_a.z += va.z; acc_a.w += va.w;
            acc_l.x = fmaf(w, vl.x, acc_l.x);
            acc_l.y = fmaf(w, vl.y, acc_l.y);
            acc_l.z = fmaf(w, vl.z, acc_l.z);
            acc_l.w = fmaf(w, vl.w, acc_l.w);
        }
    }
    if (j < end) {
        int m = end - j;
        int rr0   = (lane < m) ? __ldg(&csr_src[j + lane]) : 0;
        float ww0 = (lane < m) ? __ldg(&csr_w[j + lane]) : 0.f;
#pragma unroll 4
        for (int i = 0; i < m; i++) {
            int rr  = __shfl_sync(0xffffffffu, rr0, i);
            float w = __shfl_sync(0xffffffffu, ww0, i);
            float4 va = __ldg(&xwa[rr * 32 + lane]);
            float4 vl = __ldg(&xwl[rr * 32 + lane]);
            acc_a.x += va.x; acc_a.y += va.y; acc_a.z += va.z; acc_a.w += va.w;
            acc_l.x = fmaf(w, vl.x, acc_l.x);
            acc_l.y = fmaf(w, vl.y, acc_l.y);
            acc_l.z = fmaf(w, vl.z, acc_l.z);
            acc_l.w = fmaf(w, vl.w, acc_l.w);
        }
    }

    // finalize conv outputs: z = dinv[dst] * acc + bias
    float da = __ldg(&dinva[node]);
    float dl = __ldg(&dinvl[node]);
    float4 ba4 = __ldg(&((const float4*)b_adj)[lane]);
    float4 bl4 = __ldg(&((const float4*)b_lab)[lane]);
    float z0[4], z1[4];
    z0[0] = fmaf(da, acc_a.x, ba4.x); z0[1] = fmaf(da, acc_a.y, ba4.y);
    z0[2] = fmaf(da, acc_a.z, ba4.z); z0[3] = fmaf(da, acc_a.w, ba4.w);
    z1[0] = fmaf(dl, acc_l.x, bl4.x); z1[1] = fmaf(dl, acc_l.y, bl4.y);
    z1[2] = fmaf(dl, acc_l.z, bl4.z); z1[3] = fmaf(dl, acc_l.w, bl4.w);

    // attention over the 2 views; lane owns features [4*lane, 4*lane+4)
    float w0 = 0.f, w1 = 0.f;
    const float4* ap1t4 = (const float4*)s_ap1t;
#pragma unroll
    for (int jj = 0; jj < ATT; jj++) {
        float4 a = ap1t4[jj * 32 + lane];
        float p0 = z0[0] * a.x + z0[1] * a.y + z0[2] * a.z + z0[3] * a.w;
        float p1 = z1[0] * a.x + z1[1] * a.y + z1[2] * a.z + z1[3] * a.w;
#pragma unroll
        for (int o = 16; o > 0; o >>= 1) {
            p0 += __shfl_xor_sync(0xffffffffu, p0, o);
            p1 += __shfl_xor_sync(0xffffffffu, p1, o);
        }
        w0 = fmaf(tanhf(p0 + s_b[jj]), s_a2[jj], w0);
        w1 = fmaf(tanhf(p1 + s_b[jj]), s_a2[jj], w1);
    }
    float beta0 = 1.f / (1.f + expf(w1 - w0));  // softmax over 2 views
    float beta1 = 1.f - beta0;

    float4 o4;
    o4.x = beta0 * z0[0] + beta1 * z1[0];
    o4.y = beta0 * z0[1] + beta1 * z1[1];
    o4.z = beta0 * z0[2] + beta1 * z1[2];
    o4.w = beta0 * z0[3] + beta1 * z1[3];
    if (do_relu) {
        o4.x = fmaxf(o4.x, 0.f); o4.y = fmaxf(o4.y, 0.f);
        o4.z = fmaxf(o4.z, 0.f); o4.w = fmaxf(o4.w, 0.f);
    }
    xout[node * 32 + lane] = o4;
}

// ---------------- host orchestration ----------------
extern "C" void kernel_launch(void* const* d_in, const int* in_sizes, int n_in,
                              void* d_out, int out_size) {
    const float* x_in  = (const float*)d_in[0];
    const float* y_in  = (const float*)d_in[1];
    const int*   row   = (const int*)d_in[2];
    const int*   col   = (const int*)d_in[3];
    const float* ews   = (const float*)d_in[4];  // [2, E]
    const float* W0    = (const float*)d_in[5];
    const float* b0    = (const float*)d_in[6];
    const float* W1    = (const float*)d_in[7];
    const float* b1    = (const float*)d_in[8];
    const float* Wl    = (const float*)d_in[9];
    const float* bl    = (const float*)d_in[10];
    const float* ap1   = (const float*)d_in[11];
    const float* apb1  = (const float*)d_in[12];
    const float* ap2   = (const float*)d_in[13];
    const float* mW    = (const float*)d_in[14];
    const float* mb    = (const float*)d_in[15];
    float* out = (float*)d_out;

    float *xw_a, *xw_l, *xbuf, *ybuf;
    float *dinva, *dinvl0, *dinvl1, *degl0, *degl1, *csr_w0, *csr_w1;
    int *counts, *off, *cursor, *csr_src, *bsum;
    cudaGetSymbolAddress((void**)&xw_a,   g_xw_a);
    cudaGetSymbolAddress((void**)&xw_l,   g_xw_l);
    cudaGetSymbolAddress((void**)&xbuf,   g_xbuf);
    cudaGetSymbolAddress((void**)&ybuf,   g_ybuf);
    cudaGetSymbolAddress((void**)&counts, g_counts);
    cudaGetSymbolAddress((void**)&off,    g_off);
    cudaGetSymbolAddress((void**)&cursor, g_cursor);
    cudaGetSymbolAddress((void**)&bsum,   g_bsum);
    cudaGetSymbolAddress((void**)&csr_src, g_csr_src);
    cudaGetSymbolAddress((void**)&csr_w0, g_csr_w0);
    cudaGetSymbolAddress((void**)&csr_w1, g_csr_w1);
    cudaGetSymbolAddress((void**)&dinva,  g_dinva);
    cudaGetSymbolAddress((void**)&dinvl0, g_dinvl0);
    cudaGetSymbolAddress((void**)&dinvl1, g_dinvl1);
    cudaGetSymbolAddress((void**)&degl0,  g_degl0);
    cudaGetSymbolAddress((void**)&degl1,  g_degl1);

    const float* ew0 = ews;
    const float* ew1 = ews + EE;

    const int n_blocks   = (NN + 255) / 256;
    const int e_blocks   = (EE + 255) / 256;
    const int scan_blk   = (NN + 1023) / 1024;   // 49
    const int gemm_blk   = (NN + 63) / 64;       // 782
    const int gf_blocks  = (NN * 32 + 255) / 256;

    // ---- CSR build (parallel scan) ----
    hist_init_k<<<n_blocks, 256>>>(counts, degl0, degl1, NN);
    hist_k<<<e_blocks, 256>>>(col, ew0, ew1, counts, degl0, degl1, EE);
    dinv_k<<<n_blocks, 256>>>(counts, degl0, degl1, dinva, dinvl0, dinvl1, NN);
    scan_partials_k<<<scan_blk, 1024>>>(counts, bsum, NN);
    scan_bsums_k<<<1, 32>>>(bsum, off + NN, scan_blk);
    scan_final_k<<<scan_blk, 1024>>>(counts, bsum, off, cursor, NN);
    csr_scatter_k<<<e_blocks, 256>>>(row, col, ew0, ew1, cursor,
                                     csr_src, csr_w0, csr_w1, EE);

    const float* convW[2] = {W0, W1};
    const float* convB[2] = {b0, b1};
    const float* dinvl[2] = {dinvl0, dinvl1};
    const float* csrw[2]  = {csr_w0, csr_w1};

    for (int layer = 0; layer < 2; layer++) {
        const float* Xin = (layer == 0) ? x_in : xbuf;
        const float* Yin = (layer == 0) ? y_in : ybuf;
        int last = (layer == 1);
        float* xout = last ? out : xbuf;
        float* yout = last ? (out + (size_t)NN * HIDD) : ybuf;

        gemm_t<HIDD, HIDD, 0><<<gemm_blk, 256>>>(Xin, convW[layer], dinva, xw_a, NN);
        gemm_t<CLSS, HIDD, 0><<<gemm_blk, 256>>>(Yin, Wl, dinvl[layer], xw_l, NN);

        gather_fuse_k<<<gf_blocks, 256>>>((const float4*)xw_a, (const float4*)xw_l,
                                          off, csr_src, csrw[layer],
                                          dinva, dinvl[layer],
                                          convB[layer], bl, ap1, apb1, ap2,
                                          (float4*)xout, last ? 0 : 1, NN);

        gemm_t<HIDD, CLSS, 1><<<gemm_blk, 128>>>(xout, mW, mb, yout, NN);
    }
}